// round 1
// baseline (speedup 1.0000x reference)
#include <cuda_runtime.h>

#define N_NODES 10000
#define N_EDGES 640000
#define D       128
#define D_IN3   384   // (K_HOPS+1)*D
#define LN_EPS  1e-5f

// ---------------- scratch (device globals; no allocation allowed) -----------
__device__ float g_deg [N_NODES];
__device__ float g_norm[N_NODES];
__device__ float g_f1  [N_NODES * D];   // un-normalized hop-1 aggregate
__device__ float g_f2  [N_NODES * D];   // un-normalized hop-2 aggregate

// ---------------- zero scratch ----------------------------------------------
__global__ void zero_kernel() {
    int i = blockIdx.x * blockDim.x + threadIdx.x;
    if (i < N_NODES) g_deg[i] = 0.0f;
    if (i < N_NODES * D) {
        g_f1[i] = 0.0f;
        g_f2[i] = 0.0f;
    }
}

// ---------------- degree + norm ---------------------------------------------
__global__ void deg_kernel(const int* __restrict__ dst) {
    int e = blockIdx.x * blockDim.x + threadIdx.x;
    if (e < N_EDGES) {
        float* p = &g_deg[dst[e]];
        asm volatile("red.global.add.f32 [%0], %1;" :: "l"(p), "f"(1.0f) : "memory");
    }
}

__global__ void norm_kernel() {
    int i = blockIdx.x * blockDim.x + threadIdx.x;
    if (i < N_NODES) g_norm[i] = rsqrtf(fmaxf(g_deg[i], 1.0f));
}

// ---------------- propagation hop -------------------------------------------
// One warp per edge (grid-stride). Lane t handles features [4t, 4t+4).
// hop==0: feat = h,   coef = w * norm[src],   acc = g_f1
// hop==1: feat = g_f1, coef = w * norm[src]^2, acc = g_f2
__global__ void __launch_bounds__(256) hop_kernel(
    const float* __restrict__ h,
    const float* __restrict__ ew,
    const int*   __restrict__ src,
    const int*   __restrict__ dst,
    int hop)
{
    const float4* f4  = (hop == 0) ? (const float4*)h : (const float4*)g_f1;
    float*        acc = (hop == 0) ? g_f1 : g_f2;

    int lane   = threadIdx.x & 31;
    int warp   = (blockIdx.x * blockDim.x + threadIdx.x) >> 5;
    int nwarps = (gridDim.x * blockDim.x) >> 5;

    for (int e = warp; e < N_EDGES; e += nwarps) {
        int   s = __ldg(&src[e]);
        int   d = __ldg(&dst[e]);
        float n = __ldg(&g_norm[s]);
        float coef = __ldg(&ew[e]) * (hop ? n * n : n);

        float4 v = __ldg(&f4[s * 32 + lane]);
        v.x *= coef; v.y *= coef; v.z *= coef; v.w *= coef;

        float* p = acc + d * D + lane * 4;
        asm volatile("red.global.add.v4.f32 [%0], {%1,%2,%3,%4};"
                     :: "l"(p), "f"(v.x), "f"(v.y), "f"(v.z), "f"(v.w)
                     : "memory");
    }
}

// ---------------- fused GEMM + bias + LayerNorm + ReLU ----------------------
// Block = 128 threads (thread j = output channel j), TM=16 nodes per block.
// feats[m] = [ h[node], f1raw[node]*norm, f2raw[node]*norm ]  (384 floats)
__global__ void __launch_bounds__(128) out_kernel(
    const float* __restrict__ h,
    const float* __restrict__ W,      // [128, 384] row-major
    const float* __restrict__ bias,
    const float* __restrict__ gamma,
    const float* __restrict__ beta,
    float* __restrict__ out)
{
    constexpr int TM = 16;
    __shared__ __align__(16) float sf[TM][D_IN3];
    __shared__ float sx[TM][D];
    __shared__ float smu[TM], srs[TM];

    int j     = threadIdx.x;          // 0..127
    int node0 = blockIdx.x * TM;

    // load feature tile (96 float4 per node)
    for (int idx = j; idx < TM * 96; idx += 128) {
        int m = idx / 96, c = idx % 96;
        int node = node0 + m;
        float4 v;
        if (c < 32) {
            v = __ldg(&((const float4*)h)[node * 32 + c]);
        } else {
            float nn = g_norm[node];
            const float4* ptr = (c < 64) ? (const float4*)g_f1 : (const float4*)g_f2;
            int cc = (c < 64) ? (c - 32) : (c - 64);
            v = ptr[node * 32 + cc];
            v.x *= nn; v.y *= nn; v.z *= nn; v.w *= nn;
        }
        ((float4*)&sf[m][0])[c] = v;
    }
    __syncthreads();

    // per-thread GEMM: acc[m] = W[j,:] . feats[m,:]
    float acc[TM];
#pragma unroll
    for (int m = 0; m < TM; m++) acc[m] = 0.0f;

    const float4* W4 = (const float4*)(W + j * D_IN3);
#pragma unroll 4
    for (int k = 0; k < 96; k++) {
        float4 w = __ldg(&W4[k]);
#pragma unroll
        for (int m = 0; m < TM; m++) {
            float4 f = ((const float4*)&sf[m][0])[k];   // warp-broadcast LDS
            acc[m] += w.x * f.x + w.y * f.y + w.z * f.z + w.w * f.w;
        }
    }

    float bj = __ldg(&bias[j]);
#pragma unroll
    for (int m = 0; m < TM; m++) sx[m][j] = acc[m] + bj;
    __syncthreads();

    // LayerNorm stats: each warp reduces 4 rows
    int warp = j >> 5, lane = j & 31;
    for (int m = warp; m < TM; m += 4) {
        float s = 0.0f, ss = 0.0f;
#pragma unroll
        for (int c = lane; c < D; c += 32) {
            float v = sx[m][c];
            s += v; ss += v * v;
        }
#pragma unroll
        for (int o = 16; o; o >>= 1) {
            s  += __shfl_xor_sync(0xffffffffu, s,  o);
            ss += __shfl_xor_sync(0xffffffffu, ss, o);
        }
        if (lane == 0) {
            float mu  = s * (1.0f / D);
            float var = ss * (1.0f / D) - mu * mu;
            smu[m] = mu;
            srs[m] = rsqrtf(var + LN_EPS);
        }
    }
    __syncthreads();

    float g  = __ldg(&gamma[j]);
    float be = __ldg(&beta[j]);
#pragma unroll
    for (int m = 0; m < TM; m++) {
        float v = (sx[m][j] - smu[m]) * srs[m] * g + be;
        out[(node0 + m) * D + j] = fmaxf(v, 0.0f);
    }
}

// ---------------- launch -----------------------------------------------------
extern "C" void kernel_launch(void* const* d_in, const int* in_sizes, int n_in,
                              void* d_out, int out_size)
{
    const float* h     = (const float*)d_in[0];
    const float* ew    = (const float*)d_in[1];
    const float* W     = (const float*)d_in[2];
    const float* bias  = (const float*)d_in[3];
    const float* gamma = (const float*)d_in[4];
    const float* beta  = (const float*)d_in[5];
    const int*   src   = (const int*)d_in[6];
    const int*   dst   = (const int*)d_in[7];
    float*       out   = (float*)d_out;

    zero_kernel<<<(N_NODES * D + 255) / 256, 256>>>();
    deg_kernel<<<(N_EDGES + 255) / 256, 256>>>(dst);
    norm_kernel<<<(N_NODES + 255) / 256, 256>>>();

    const int hopBlocks = 1184;   // 8 blocks/SM * 148 SMs, grid-stride over edges
    hop_kernel<<<hopBlocks, 256>>>(h, ew, src, dst, 0);
    hop_kernel<<<hopBlocks, 256>>>(h, ew, src, dst, 1);

    out_kernel<<<N_NODES / 16, 128>>>(h, W, bias, gamma, beta, out);
}

// round 2
// speedup vs baseline: 1.2127x; 1.2127x over previous
#include <cuda_runtime.h>

#define N_NODES 10000
#define N_EDGES 640000
#define D       128
#define D_IN3   384   // (K_HOPS+1)*D
#define LN_EPS  1e-5f

// ---------------- scratch (device globals; no allocation allowed) -----------
__device__ int   g_cnt [N_NODES];        // in-degree histogram
__device__ int   g_row [N_NODES + 1];    // CSR row offsets (by dst)
__device__ int   g_woff[N_NODES];        // scatter write cursors
__device__ float g_norm[N_NODES];
__device__ int   g_esrc[N_EDGES];        // src, sorted by dst
__device__ float g_ec1 [N_EDGES];        // w * norm[src]
__device__ float g_ec2 [N_EDGES];        // w * norm[src]^2
__device__ float g_f1  [N_NODES * D];    // un-normalized hop-1 aggregate
__device__ float g_f2  [N_NODES * D];    // un-normalized hop-2 aggregate

// ---------------- zero counters ----------------------------------------------
__global__ void zero_kernel() {
    int i = blockIdx.x * blockDim.x + threadIdx.x;
    if (i < N_NODES) g_cnt[i] = 0;
}

// ---------------- histogram of dst (= in-degree) ------------------------------
__global__ void hist_kernel(const int* __restrict__ dst) {
    int e = blockIdx.x * blockDim.x + threadIdx.x;
    if (e < N_EDGES) {
        int* p = &g_cnt[dst[e]];
        asm volatile("red.global.add.u32 [%0], %1;" :: "l"(p), "r"(1) : "memory");
    }
}

// ---------------- single-block prefix scan + norm -----------------------------
// 256 threads, each owns a chunk of 40 nodes (256*40 = 10240 >= 10000).
__global__ void __launch_bounds__(256) scan_kernel() {
    __shared__ int ts[256];
    int t = threadIdx.x;
    int b = t * 40;
    int e = min(b + 40, N_NODES);

    int s = 0;
    for (int i = b; i < e; i++) s += g_cnt[i];
    ts[t] = s;
    __syncthreads();

    // Hillis-Steele inclusive scan over 256 thread totals
    for (int o = 1; o < 256; o <<= 1) {
        int v = (t >= o) ? ts[t - o] : 0;
        __syncthreads();
        ts[t] += v;
        __syncthreads();
    }
    int off = (t == 0) ? 0 : ts[t - 1];   // exclusive prefix for this chunk

    for (int i = b; i < e; i++) {
        int c = g_cnt[i];
        g_row[i]  = off;
        g_woff[i] = off;
        g_norm[i] = rsqrtf(fmaxf((float)c, 1.0f));
        off += c;
    }
    if (t == 255) g_row[N_NODES] = N_EDGES;
}

// ---------------- scatter edges into CSR order --------------------------------
__global__ void scatter_kernel(const float* __restrict__ ew,
                               const int*   __restrict__ src,
                               const int*   __restrict__ dst) {
    int e = blockIdx.x * blockDim.x + threadIdx.x;
    if (e < N_EDGES) {
        int d   = dst[e];
        int pos = atomicAdd(&g_woff[d], 1);
        int s   = src[e];
        float n = __ldg(&g_norm[s]);
        float c1 = __ldg(&ew[e]) * n;
        g_esrc[pos] = s;
        g_ec1[pos]  = c1;
        g_ec2[pos]  = c1 * n;
    }
}

// ---------------- gather-based propagation hop --------------------------------
// One block (128 threads) per dst node; thread t owns feature t.
__global__ void __launch_bounds__(128) hop_csr(const float* __restrict__ feat,
                                               const float* __restrict__ ec,
                                               float* __restrict__ out) {
    __shared__ int   ssrc[128];
    __shared__ float sc[128];

    int node = blockIdx.x;
    int t    = threadIdx.x;
    int beg  = g_row[node];
    int end  = g_row[node + 1];

    float acc = 0.0f;
    for (int base = beg; base < end; base += 128) {
        int n = min(128, end - base);
        if (t < n) {
            ssrc[t] = g_esrc[base + t] * D;
            sc[t]   = g_ec1 == ec ? g_ec1[base + t] : g_ec2[base + t];
        }
        __syncthreads();
#pragma unroll 4
        for (int i = 0; i < n; i++) {
            acc += sc[i] * __ldg(&feat[ssrc[i] + t]);
        }
        __syncthreads();
    }
    out[node * D + t] = acc;
}

// ---------------- fused GEMM + bias + LayerNorm + ReLU ----------------------
__global__ void __launch_bounds__(128) out_kernel(
    const float* __restrict__ h,
    const float* __restrict__ W,      // [128, 384] row-major
    const float* __restrict__ bias,
    const float* __restrict__ gamma,
    const float* __restrict__ beta,
    float* __restrict__ out)
{
    constexpr int TM = 16;
    __shared__ __align__(16) float sf[TM][D_IN3];
    __shared__ float sx[TM][D];
    __shared__ float smu[TM], srs[TM];

    int j     = threadIdx.x;          // 0..127 = output channel
    int node0 = blockIdx.x * TM;

    // load feature tile (96 float4 per node)
    for (int idx = j; idx < TM * 96; idx += 128) {
        int m = idx / 96, c = idx % 96;
        int node = node0 + m;
        float4 v;
        if (c < 32) {
            v = __ldg(&((const float4*)h)[node * 32 + c]);
        } else {
            float nn = g_norm[node];
            const float4* ptr = (c < 64) ? (const float4*)g_f1 : (const float4*)g_f2;
            int cc = (c < 64) ? (c - 32) : (c - 64);
            v = ptr[node * 32 + cc];
            v.x *= nn; v.y *= nn; v.z *= nn; v.w *= nn;
        }
        ((float4*)&sf[m][0])[c] = v;
    }
    __syncthreads();

    float acc[TM];
#pragma unroll
    for (int m = 0; m < TM; m++) acc[m] = 0.0f;

    const float4* W4 = (const float4*)(W + j * D_IN3);
#pragma unroll 4
    for (int k = 0; k < 96; k++) {
        float4 w = __ldg(&W4[k]);
#pragma unroll
        for (int m = 0; m < TM; m++) {
            float4 f = ((const float4*)&sf[m][0])[k];
            acc[m] += w.x * f.x + w.y * f.y + w.z * f.z + w.w * f.w;
        }
    }

    float bj = __ldg(&bias[j]);
#pragma unroll
    for (int m = 0; m < TM; m++) sx[m][j] = acc[m] + bj;
    __syncthreads();

    int warp = j >> 5, lane = j & 31;
    for (int m = warp; m < TM; m += 4) {
        float s = 0.0f, ss = 0.0f;
#pragma unroll
        for (int c = lane; c < D; c += 32) {
            float v = sx[m][c];
            s += v; ss += v * v;
        }
#pragma unroll
        for (int o = 16; o; o >>= 1) {
            s  += __shfl_xor_sync(0xffffffffu, s,  o);
            ss += __shfl_xor_sync(0xffffffffu, ss, o);
        }
        if (lane == 0) {
            float mu  = s * (1.0f / D);
            float var = ss * (1.0f / D) - mu * mu;
            smu[m] = mu;
            srs[m] = rsqrtf(var + LN_EPS);
        }
    }
    __syncthreads();

    float g  = __ldg(&gamma[j]);
    float be = __ldg(&beta[j]);
#pragma unroll
    for (int m = 0; m < TM; m++) {
        float v = (sx[m][j] - smu[m]) * srs[m] * g + be;
        out[(node0 + m) * D + j] = fmaxf(v, 0.0f);
    }
}

// ---------------- launch -----------------------------------------------------
extern "C" void kernel_launch(void* const* d_in, const int* in_sizes, int n_in,
                              void* d_out, int out_size)
{
    const float* h     = (const float*)d_in[0];
    const float* ew    = (const float*)d_in[1];
    const float* W     = (const float*)d_in[2];
    const float* bias  = (const float*)d_in[3];
    const float* gamma = (const float*)d_in[4];
    const float* beta  = (const float*)d_in[5];
    const int*   src   = (const int*)d_in[6];
    const int*   dst   = (const int*)d_in[7];
    float*       out   = (float*)d_out;

    zero_kernel<<<(N_NODES + 255) / 256, 256>>>();
    hist_kernel<<<(N_EDGES + 255) / 256, 256>>>(dst);
    scan_kernel<<<1, 256>>>();
    scatter_kernel<<<(N_EDGES + 255) / 256, 256>>>(ew, src, dst);

    // resolve device-global addresses host-side is not allowed; hop_csr takes
    // plain pointers via a tiny launcher using the globals' device addresses.
    // We can't take &g_f1 on host, so use kernels that reference globals
    // directly through parameters obtained via cudaGetSymbolAddress-free path:
    // simplest: pass nullptrs replaced by overloads below.
    // Instead: launch with device-symbol pointers via separate wrapper kernels.
    // (hop_csr already reads g_row/g_esrc/g_ec* directly; feat/out passed in.)
    {
        // hop 1: feat = h, coef = c1, out = g_f1
        void* f1ptr; cudaGetSymbolAddress(&f1ptr, g_f1);
        void* f2ptr; cudaGetSymbolAddress(&f2ptr, g_f2);
        void* c1ptr; cudaGetSymbolAddress(&c1ptr, g_ec1);
        void* c2ptr; cudaGetSymbolAddress(&c2ptr, g_ec2);
        hop_csr<<<N_NODES, 128>>>(h, (const float*)c1ptr, (float*)f1ptr);
        hop_csr<<<N_NODES, 128>>>((const float*)f1ptr, (const float*)c2ptr, (float*)f2ptr);
    }

    out_kernel<<<N_NODES / 16, 128>>>(h, W, bias, gamma, beta, out);
}

// round 3
// speedup vs baseline: 1.2845x; 1.0592x over previous
#include <cuda_runtime.h>

#define N_NODES 10000
#define N_EDGES 640000
#define D       128
#define D_IN3   384   // (K_HOPS+1)*D
#define LN_EPS  1e-5f

// ---------------- scratch (device globals; no allocation allowed) -----------
__device__ int   g_cnt [N_NODES];        // in-degree histogram
__device__ int   g_row [N_NODES + 1];    // CSR row offsets (by dst)
__device__ int   g_woff[N_NODES];        // scatter write cursors
__device__ float g_norm[N_NODES];
__device__ int4  g_erec[N_EDGES];        // {src, c1 bits, c2 bits, 0} sorted by dst
__device__ float g_f1  [N_NODES * D];    // un-normalized hop-1 aggregate
__device__ float g_f2  [N_NODES * D];    // un-normalized hop-2 aggregate

// ---------------- histogram of dst (= in-degree) ------------------------------
__global__ void hist_kernel(const int* __restrict__ dst) {
    int e = blockIdx.x * blockDim.x + threadIdx.x;
    if (e < N_EDGES) {
        int* p = &g_cnt[dst[e]];
        asm volatile("red.global.add.u32 [%0], %1;" :: "l"(p), "r"(1) : "memory");
    }
}

// ---------------- single-block prefix scan + norm -----------------------------
// 1024 threads, each owns a chunk of 10 nodes (1024*10 = 10240 >= 10000).
__global__ void __launch_bounds__(1024) scan_kernel() {
    __shared__ int ts[1024];
    int t = threadIdx.x;
    int b = t * 10;
    int e = min(b + 10, N_NODES);

    int s = 0;
    for (int i = b; i < e; i++) s += g_cnt[i];
    ts[t] = s;
    __syncthreads();

    for (int o = 1; o < 1024; o <<= 1) {
        int v = (t >= o) ? ts[t - o] : 0;
        __syncthreads();
        ts[t] += v;
        __syncthreads();
    }
    int off = (t == 0) ? 0 : ts[t - 1];   // exclusive prefix for this chunk

    for (int i = b; i < e; i++) {
        int c = g_cnt[i];
        g_row[i]  = off;
        g_woff[i] = off;
        g_norm[i] = rsqrtf(fmaxf((float)c, 1.0f));
        off += c;
    }
    if (t == 1023) g_row[N_NODES] = N_EDGES;
}

// ---------------- scatter edges into CSR order (packed records) --------------
__global__ void __launch_bounds__(256) scatter_kernel(
    const float* __restrict__ ew,
    const int*   __restrict__ src,
    const int*   __restrict__ dst)
{
    int e0 = (blockIdx.x * blockDim.x + threadIdx.x) * 2;
#pragma unroll
    for (int k = 0; k < 2; k++) {
        int e = e0 + k;
        if (e < N_EDGES) {
            int d   = __ldg(&dst[e]);
            int s   = __ldg(&src[e]);
            float w = __ldg(&ew[e]);
            int pos = atomicAdd(&g_woff[d], 1);
            float n  = __ldg(&g_norm[s]);
            float c1 = w * n;
            int4 r;
            r.x = s;
            r.y = __float_as_int(c1);
            r.z = __float_as_int(c1 * n);
            r.w = 0;
            g_erec[pos] = r;
        }
    }
}

// ---------------- gather-based propagation hop (warp per node) ----------------
// Lane t owns features [4t, 4t+4) via float4. SECOND selects c1 vs c2.
template <int SECOND>
__global__ void __launch_bounds__(256) hop_csr(const float4* __restrict__ feat4,
                                               float4* __restrict__ out4)
{
    int lane = threadIdx.x & 31;
    int node = (blockIdx.x * blockDim.x + threadIdx.x) >> 5;
    if (node >= N_NODES) return;

    int beg = g_row[node];
    int end = g_row[node + 1];

    float4 acc = make_float4(0.f, 0.f, 0.f, 0.f);
    for (int base = beg; base < end; base += 32) {
        int n = min(32, end - base);
        int4 rec = make_int4(0, 0, 0, 0);
        if (lane < n) rec = __ldg(&g_erec[base + lane]);
        int cbits_own = SECOND ? rec.z : rec.y;

        for (int i = 0; i < n; i++) {
            int   s = __shfl_sync(0xffffffffu, rec.x, i);
            float c = __int_as_float(__shfl_sync(0xffffffffu, cbits_own, i));
            float4 v = __ldg(&feat4[s * 32 + lane]);
            acc.x += c * v.x;
            acc.y += c * v.y;
            acc.z += c * v.z;
            acc.w += c * v.w;
        }
    }
    out4[node * 32 + lane] = acc;
}

// ---------------- fused GEMM + bias + LayerNorm + ReLU ----------------------
__global__ void __launch_bounds__(128) out_kernel(
    const float* __restrict__ h,
    const float* __restrict__ W,      // [128, 384] row-major
    const float* __restrict__ bias,
    const float* __restrict__ gamma,
    const float* __restrict__ beta,
    float* __restrict__ out)
{
    constexpr int TM = 16;
    __shared__ __align__(16) float sf[TM][D_IN3];
    __shared__ float sx[TM][D];
    __shared__ float smu[TM], srs[TM];

    int j     = threadIdx.x;          // 0..127 = output channel
    int node0 = blockIdx.x * TM;

    // load feature tile (96 float4 per node)
    for (int idx = j; idx < TM * 96; idx += 128) {
        int m = idx / 96, c = idx % 96;
        int node = node0 + m;
        float4 v;
        if (c < 32) {
            v = __ldg(&((const float4*)h)[node * 32 + c]);
        } else {
            float nn = g_norm[node];
            const float4* ptr = (c < 64) ? (const float4*)g_f1 : (const float4*)g_f2;
            int cc = (c < 64) ? (c - 32) : (c - 64);
            v = ptr[node * 32 + cc];
            v.x *= nn; v.y *= nn; v.z *= nn; v.w *= nn;
        }
        ((float4*)&sf[m][0])[c] = v;
    }
    __syncthreads();

    float acc[TM];
#pragma unroll
    for (int m = 0; m < TM; m++) acc[m] = 0.0f;

    const float4* W4 = (const float4*)(W + j * D_IN3);
#pragma unroll 4
    for (int k = 0; k < 96; k++) {
        float4 w = __ldg(&W4[k]);
#pragma unroll
        for (int m = 0; m < TM; m++) {
            float4 f = ((const float4*)&sf[m][0])[k];
            acc[m] += w.x * f.x + w.y * f.y + w.z * f.z + w.w * f.w;
        }
    }

    float bj = __ldg(&bias[j]);
#pragma unroll
    for (int m = 0; m < TM; m++) sx[m][j] = acc[m] + bj;
    __syncthreads();

    int warp = j >> 5, lane = j & 31;
    for (int m = warp; m < TM; m += 4) {
        float s = 0.0f, ss = 0.0f;
#pragma unroll
        for (int c = lane; c < D; c += 32) {
            float v = sx[m][c];
            s += v; ss += v * v;
        }
#pragma unroll
        for (int o = 16; o; o >>= 1) {
            s  += __shfl_xor_sync(0xffffffffu, s,  o);
            ss += __shfl_xor_sync(0xffffffffu, ss, o);
        }
        if (lane == 0) {
            float mu  = s * (1.0f / D);
            float var = ss * (1.0f / D) - mu * mu;
            smu[m] = mu;
            srs[m] = rsqrtf(var + LN_EPS);
        }
    }
    __syncthreads();

    float g  = __ldg(&gamma[j]);
    float be = __ldg(&beta[j]);
#pragma unroll
    for (int m = 0; m < TM; m++) {
        float v = (sx[m][j] - smu[m]) * srs[m] * g + be;
        out[(node0 + m) * D + j] = fmaxf(v, 0.0f);
    }
}

// ---------------- launch -----------------------------------------------------
extern "C" void kernel_launch(void* const* d_in, const int* in_sizes, int n_in,
                              void* d_out, int out_size)
{
    const float* h     = (const float*)d_in[0];
    const float* ew    = (const float*)d_in[1];
    const float* W     = (const float*)d_in[2];
    const float* bias  = (const float*)d_in[3];
    const float* gamma = (const float*)d_in[4];
    const float* beta  = (const float*)d_in[5];
    const int*   src   = (const int*)d_in[6];
    const int*   dst   = (const int*)d_in[7];
    float*       out   = (float*)d_out;

    void* cntPtr; cudaGetSymbolAddress(&cntPtr, g_cnt);
    void* f1Ptr;  cudaGetSymbolAddress(&f1Ptr,  g_f1);
    void* f2Ptr;  cudaGetSymbolAddress(&f2Ptr,  g_f2);

    cudaMemsetAsync(cntPtr, 0, N_NODES * sizeof(int));
    hist_kernel<<<(N_EDGES + 255) / 256, 256>>>(dst);
    scan_kernel<<<1, 1024>>>();
    scatter_kernel<<<(N_EDGES / 2 + 255) / 256, 256>>>(ew, src, dst);

    const int hopBlocks = (N_NODES * 32 + 255) / 256;   // warp per node
    hop_csr<0><<<hopBlocks, 256>>>((const float4*)h, (float4*)f1Ptr);
    hop_csr<1><<<hopBlocks, 256>>>((const float4*)f1Ptr, (float4*)f2Ptr);

    out_kernel<<<N_NODES / 16, 128>>>(h, W, bias, gamma, beta, out);
}

// round 4
// speedup vs baseline: 1.5777x; 1.2282x over previous
#include <cuda_runtime.h>

#define N_NODES 10000
#define N_EDGES 640000
#define D       128
#define D_IN3   384   // (K_HOPS+1)*D
#define LN_EPS  1e-5f

// ---------------- scratch (device globals; no allocation allowed) -----------
__device__ int   g_cnt [N_NODES];        // in-degree histogram
__device__ int   g_row [N_NODES + 1];    // CSR row offsets (by dst)
__device__ int   g_woff[N_NODES];        // scatter write cursors
__device__ float g_norm[N_NODES];
__device__ int4  g_erec[N_EDGES];        // {src, c1 bits, c2 bits, 0} sorted by dst
__device__ float g_f1  [N_NODES * D];    // un-normalized hop-1 aggregate
__device__ float g_f2  [N_NODES * D];    // un-normalized hop-2 aggregate

// ---------------- histogram of dst (= in-degree) ------------------------------
__global__ void hist_kernel(const int* __restrict__ dst) {
    int e = blockIdx.x * blockDim.x + threadIdx.x;
    if (e < N_EDGES) {
        int* p = &g_cnt[dst[e]];
        asm volatile("red.global.add.u32 [%0], %1;" :: "l"(p), "r"(1) : "memory");
    }
}

// ---------------- single-block prefix scan + norm -----------------------------
__global__ void __launch_bounds__(1024) scan_kernel() {
    __shared__ int ts[1024];
    int t = threadIdx.x;
    int b = t * 10;
    int e = min(b + 10, N_NODES);

    int s = 0;
    for (int i = b; i < e; i++) s += g_cnt[i];
    ts[t] = s;
    __syncthreads();

    for (int o = 1; o < 1024; o <<= 1) {
        int v = (t >= o) ? ts[t - o] : 0;
        __syncthreads();
        ts[t] += v;
        __syncthreads();
    }
    int off = (t == 0) ? 0 : ts[t - 1];

    for (int i = b; i < e; i++) {
        int c = g_cnt[i];
        g_row[i]  = off;
        g_woff[i] = off;
        g_norm[i] = rsqrtf(fmaxf((float)c, 1.0f));
        off += c;
    }
    if (t == 1023) g_row[N_NODES] = N_EDGES;
}

// ---------------- scatter edges into CSR order (packed records) --------------
__global__ void __launch_bounds__(256) scatter_kernel(
    const float* __restrict__ ew,
    const int*   __restrict__ src,
    const int*   __restrict__ dst)
{
    int e0 = (blockIdx.x * blockDim.x + threadIdx.x) * 2;
#pragma unroll
    for (int k = 0; k < 2; k++) {
        int e = e0 + k;
        if (e < N_EDGES) {
            int d   = __ldg(&dst[e]);
            int s   = __ldg(&src[e]);
            float w = __ldg(&ew[e]);
            int pos = atomicAdd(&g_woff[d], 1);
            float n  = __ldg(&g_norm[s]);
            float c1 = w * n;
            int4 r;
            r.x = s;
            r.y = __float_as_int(c1);
            r.z = __float_as_int(c1 * n);
            r.w = 0;
            g_erec[pos] = r;
        }
    }
}

// ---------------- gather-based propagation hop (warp per node) ----------------
// Lane t owns features [4t, 4t+4) via float4. SECOND selects c1 vs c2.
// Full 32-edge chunks use a compile-time-unrolled loop so ptxas can pipeline
// many independent LDG.128 gathers; only the tail runs the dynamic loop.
template <int SECOND>
__global__ void __launch_bounds__(256, 3) hop_csr(const float4* __restrict__ feat4,
                                                  float4* __restrict__ out4)
{
    int lane = threadIdx.x & 31;
    int node = (blockIdx.x * blockDim.x + threadIdx.x) >> 5;
    if (node >= N_NODES) return;

    int beg = g_row[node];
    int end = g_row[node + 1];

    float4 acc = make_float4(0.f, 0.f, 0.f, 0.f);
    int base = beg;

    for (; base + 32 <= end; base += 32) {
        int4 rec = __ldg(&g_erec[base + lane]);
        int cb = SECOND ? rec.z : rec.y;
#pragma unroll
        for (int i = 0; i < 32; i++) {
            int   s = __shfl_sync(0xffffffffu, rec.x, i);
            float c = __int_as_float(__shfl_sync(0xffffffffu, cb, i));
            float4 v = __ldg(&feat4[s * 32 + lane]);
            acc.x = fmaf(c, v.x, acc.x);
            acc.y = fmaf(c, v.y, acc.y);
            acc.z = fmaf(c, v.z, acc.z);
            acc.w = fmaf(c, v.w, acc.w);
        }
    }

    int n = end - base;
    if (n > 0) {
        int4 rec = make_int4(0, 0, 0, 0);
        if (lane < n) rec = __ldg(&g_erec[base + lane]);
        int cb = SECOND ? rec.z : rec.y;
        for (int i = 0; i < n; i++) {
            int   s = __shfl_sync(0xffffffffu, rec.x, i);
            float c = __int_as_float(__shfl_sync(0xffffffffu, cb, i));
            float4 v = __ldg(&feat4[s * 32 + lane]);
            acc.x = fmaf(c, v.x, acc.x);
            acc.y = fmaf(c, v.y, acc.y);
            acc.z = fmaf(c, v.z, acc.z);
            acc.w = fmaf(c, v.w, acc.w);
        }
    }
    out4[node * 32 + lane] = acc;
}

// ---------------- 3xTF32 helpers ---------------------------------------------
__device__ __forceinline__ unsigned f2tf(float x) {
    unsigned r;
    asm("cvt.rna.tf32.f32 %0, %1;" : "=r"(r) : "f"(x));
    return r;
}

__device__ __forceinline__ void mma8(float* d, const unsigned* a, const unsigned* b) {
    asm volatile("mma.sync.aligned.m16n8k8.row.col.f32.tf32.tf32.f32 "
                 "{%0,%1,%2,%3},{%4,%5,%6,%7},{%8,%9},{%0,%1,%2,%3};"
                 : "+f"(d[0]), "+f"(d[1]), "+f"(d[2]), "+f"(d[3])
                 : "r"(a[0]), "r"(a[1]), "r"(a[2]), "r"(a[3]),
                   "r"(b[0]), "r"(b[1]));
}

// ---------------- fused GEMM (3xTF32 mma) + bias + LayerNorm + ReLU ----------
// Block = 128 threads (4 warps), TM=16 nodes. Warp w owns output cols
// [32w, 32w+32) as 4 n-tiles of 8. K=384 = 48 k-steps of 8.
#define SAPAD 388   // 388 mod 32 = 4 -> conflict-free m16k8 A-fragment LDS
__global__ void __launch_bounds__(128) out_kernel(
    const float* __restrict__ h,
    const float* __restrict__ W,      // [128, 384] row-major
    const float* __restrict__ bias,
    const float* __restrict__ gamma,
    const float* __restrict__ beta,
    float* __restrict__ out)
{
    constexpr int TM = 16;
    __shared__ float sA[TM][SAPAD];
    __shared__ float sx[TM][D];
    __shared__ float smu[TM], srs[TM];

    int tid   = threadIdx.x;
    int warp  = tid >> 5;
    int lane  = tid & 31;
    int node0 = blockIdx.x * TM;

    // ---- load feature tile: feats = [h, f1*norm, f2*norm], 96 float4/node ----
    for (int idx = tid; idx < TM * 96; idx += 128) {
        int m = idx / 96, c = idx % 96;
        int node = node0 + m;
        float4 v;
        if (c < 32) {
            v = __ldg(&((const float4*)h)[node * 32 + c]);
        } else {
            float nn = g_norm[node];
            const float4* ptr = (c < 64) ? (const float4*)g_f1 : (const float4*)g_f2;
            int cc = (c < 64) ? (c - 32) : (c - 64);
            v = ptr[node * 32 + cc];
            v.x *= nn; v.y *= nn; v.z *= nn; v.w *= nn;
        }
        *(float4*)&sA[m][c * 4] = v;
    }
    __syncthreads();

    // ---- 3xTF32 mma: D[16 x 32] per warp ----
    int g  = lane >> 2;   // group 0..7
    int tg = lane & 3;    // thread-in-group 0..3

    float acc[4][4];
#pragma unroll
    for (int nt = 0; nt < 4; nt++)
#pragma unroll
        for (int i = 0; i < 4; i++) acc[nt][i] = 0.0f;

#pragma unroll 4
    for (int k0 = 0; k0 < 48; k0++) {
        int kk = k0 * 8;
        float a0 = sA[g    ][kk + tg];
        float a1 = sA[g + 8][kk + tg];
        float a2 = sA[g    ][kk + tg + 4];
        float a3 = sA[g + 8][kk + tg + 4];

        unsigned ah[4] = { f2tf(a0), f2tf(a1), f2tf(a2), f2tf(a3) };
        unsigned al[4] = {
            f2tf(a0 - __uint_as_float(ah[0])),
            f2tf(a1 - __uint_as_float(ah[1])),
            f2tf(a2 - __uint_as_float(ah[2])),
            f2tf(a3 - __uint_as_float(ah[3]))
        };

#pragma unroll
        for (int nt = 0; nt < 4; nt++) {
            int n = warp * 32 + nt * 8 + g;
            float b0f = __ldg(&W[n * D_IN3 + kk + tg]);
            float b1f = __ldg(&W[n * D_IN3 + kk + tg + 4]);
            unsigned bh[2] = { f2tf(b0f), f2tf(b1f) };
            unsigned bl[2] = {
                f2tf(b0f - __uint_as_float(bh[0])),
                f2tf(b1f - __uint_as_float(bh[1]))
            };
            mma8(acc[nt], ah, bh);
            mma8(acc[nt], al, bh);
            mma8(acc[nt], ah, bl);
        }
    }

    // ---- write acc (+bias) into sx ----
#pragma unroll
    for (int nt = 0; nt < 4; nt++) {
        int col = warp * 32 + nt * 8 + 2 * tg;
        float b0 = __ldg(&bias[col]);
        float b1 = __ldg(&bias[col + 1]);
        sx[g    ][col    ] = acc[nt][0] + b0;
        sx[g    ][col + 1] = acc[nt][1] + b1;
        sx[g + 8][col    ] = acc[nt][2] + b0;
        sx[g + 8][col + 1] = acc[nt][3] + b1;
    }
    __syncthreads();

    // ---- LayerNorm stats: each warp reduces 4 rows ----
    for (int m = warp; m < TM; m += 4) {
        float s = 0.0f, ss = 0.0f;
#pragma unroll
        for (int c = lane; c < D; c += 32) {
            float v = sx[m][c];
            s += v; ss += v * v;
        }
#pragma unroll
        for (int o = 16; o; o >>= 1) {
            s  += __shfl_xor_sync(0xffffffffu, s,  o);
            ss += __shfl_xor_sync(0xffffffffu, ss, o);
        }
        if (lane == 0) {
            float mu  = s * (1.0f / D);
            float var = ss * (1.0f / D) - mu * mu;
            smu[m] = mu;
            srs[m] = rsqrtf(var + LN_EPS);
        }
    }
    __syncthreads();

    // ---- normalize + relu + store (thread j = col j) ----
    int j = tid;
    float gm = __ldg(&gamma[j]);
    float be = __ldg(&beta[j]);
#pragma unroll
    for (int m = 0; m < TM; m++) {
        float v = (sx[m][j] - smu[m]) * srs[m] * gm + be;
        out[(node0 + m) * D + j] = fmaxf(v, 0.0f);
    }
}

// ---------------- launch -----------------------------------------------------
extern "C" void kernel_launch(void* const* d_in, const int* in_sizes, int n_in,
                              void* d_out, int out_size)
{
    const float* h     = (const float*)d_in[0];
    const float* ew    = (const float*)d_in[1];
    const float* W     = (const float*)d_in[2];
    const float* bias  = (const float*)d_in[3];
    const float* gamma = (const float*)d_in[4];
    const float* beta  = (const float*)d_in[5];
    const int*   src   = (const int*)d_in[6];
    const int*   dst   = (const int*)d_in[7];
    float*       out   = (float*)d_out;

    void* cntPtr; cudaGetSymbolAddress(&cntPtr, g_cnt);
    void* f1Ptr;  cudaGetSymbolAddress(&f1Ptr,  g_f1);
    void* f2Ptr;  cudaGetSymbolAddress(&f2Ptr,  g_f2);

    cudaMemsetAsync(cntPtr, 0, N_NODES * sizeof(int));
    hist_kernel<<<(N_EDGES + 255) / 256, 256>>>(dst);
    scan_kernel<<<1, 1024>>>();
    scatter_kernel<<<(N_EDGES / 2 + 255) / 256, 256>>>(ew, src, dst);

    const int hopBlocks = (N_NODES * 32 + 255) / 256;   // warp per node
    hop_csr<0><<<hopBlocks, 256>>>((const float4*)h, (float4*)f1Ptr);
    hop_csr<1><<<hopBlocks, 256>>>((const float4*)f1Ptr, (float4*)f2Ptr);

    out_kernel<<<N_NODES / 16, 128>>>(h, W, bias, gamma, beta, out);
}

// round 5
// speedup vs baseline: 1.6056x; 1.0177x over previous
#include <cuda_runtime.h>
#include <cuda_fp16.h>

#define N_NODES 10000
#define N_EDGES 640000
#define D       128
#define D_IN3   384   // (K_HOPS+1)*D
#define LN_EPS  1e-5f

// ---------------- scratch (device globals; no allocation allowed) -----------
__device__ int   g_cnt [N_NODES];        // in-degree histogram
__device__ int   g_row [N_NODES + 1];    // CSR row offsets (by dst)
__device__ int   g_woff[N_NODES];        // scatter write cursors
__device__ float g_norm[N_NODES];
__device__ int4  g_erec[N_EDGES];        // {src, c1 bits, c2 bits, 0} sorted by dst
__device__ float g_f1  [N_NODES * D];    // un-normalized hop-1 aggregate (fp32)
__device__ float g_f2  [N_NODES * D];    // un-normalized hop-2 aggregate (fp32)
__device__ uint2 g_h16 [N_NODES * 32];   // h as fp16   (gather payload, 8B/lane)
__device__ uint2 g_f1h [N_NODES * 32];   // f1 as fp16  (gather payload, 8B/lane)

// ---------------- h -> fp16 conversion ----------------------------------------
__global__ void conv_kernel(const float4* __restrict__ h4) {
    int i = blockIdx.x * blockDim.x + threadIdx.x;   // one uint2 (4 halves)
    if (i < N_NODES * 32) {
        float4 v = __ldg(&h4[i]);
        __half2 a = __floats2half2_rn(v.x, v.y);
        __half2 b = __floats2half2_rn(v.z, v.w);
        uint2 o;
        o.x = *reinterpret_cast<unsigned*>(&a);
        o.y = *reinterpret_cast<unsigned*>(&b);
        g_h16[i] = o;
    }
}

// ---------------- histogram of dst (= in-degree) ------------------------------
__global__ void hist_kernel(const int* __restrict__ dst) {
    int e = blockIdx.x * blockDim.x + threadIdx.x;
    if (e < N_EDGES) {
        int* p = &g_cnt[dst[e]];
        asm volatile("red.global.add.u32 [%0], %1;" :: "l"(p), "r"(1) : "memory");
    }
}

// ---------------- single-block prefix scan + norm -----------------------------
__global__ void __launch_bounds__(1024) scan_kernel() {
    __shared__ int ts[1024];
    int t = threadIdx.x;
    int b = t * 10;
    int e = min(b + 10, N_NODES);

    int s = 0;
    for (int i = b; i < e; i++) s += g_cnt[i];
    ts[t] = s;
    __syncthreads();

    for (int o = 1; o < 1024; o <<= 1) {
        int v = (t >= o) ? ts[t - o] : 0;
        __syncthreads();
        ts[t] += v;
        __syncthreads();
    }
    int off = (t == 0) ? 0 : ts[t - 1];

    for (int i = b; i < e; i++) {
        int c = g_cnt[i];
        g_row[i]  = off;
        g_woff[i] = off;
        g_norm[i] = rsqrtf(fmaxf((float)c, 1.0f));
        off += c;
    }
    if (t == 1023) g_row[N_NODES] = N_EDGES;
}

// ---------------- scatter edges into CSR order (packed records) --------------
__global__ void __launch_bounds__(256) scatter_kernel(
    const float* __restrict__ ew,
    const int*   __restrict__ src,
    const int*   __restrict__ dst)
{
    int e0 = (blockIdx.x * blockDim.x + threadIdx.x) * 2;
#pragma unroll
    for (int k = 0; k < 2; k++) {
        int e = e0 + k;
        if (e < N_EDGES) {
            int d   = __ldg(&dst[e]);
            int s   = __ldg(&src[e]);
            float w = __ldg(&ew[e]);
            int pos = atomicAdd(&g_woff[d], 1);
            float n  = __ldg(&g_norm[s]);
            float c1 = w * n;
            int4 r;
            r.x = s;
            r.y = __float_as_int(c1);
            r.z = __float_as_int(c1 * n);
            r.w = 0;
            g_erec[pos] = r;
        }
    }
}

// ---------------- gather-based propagation hop (warp per node, fp16 gather) ---
// Lane t owns features [4t, 4t+4): gathers uint2 (4 halves), accumulates fp32.
// SECOND=0: feat=g_h16, coef=c1, writes f1 (fp32) + f1h (fp16)
// SECOND=1: feat=g_f1h, coef=c2, writes f2 (fp32)
template <int SECOND>
__global__ void __launch_bounds__(256, 4) hop_csr(const uint2* __restrict__ feat16,
                                                  float4* __restrict__ outf)
{
    int lane = threadIdx.x & 31;
    int node = (blockIdx.x * blockDim.x + threadIdx.x) >> 5;
    if (node >= N_NODES) return;

    int beg = g_row[node];
    int end = g_row[node + 1];

    float4 acc = make_float4(0.f, 0.f, 0.f, 0.f);
    int base = beg;

    for (; base + 32 <= end; base += 32) {
        int4 rec = __ldg(&g_erec[base + lane]);
        int cb = SECOND ? rec.z : rec.y;
#pragma unroll
        for (int i = 0; i < 32; i++) {
            int   s = __shfl_sync(0xffffffffu, rec.x, i);
            float c = __int_as_float(__shfl_sync(0xffffffffu, cb, i));
            uint2 v = __ldg(&feat16[s * 32 + lane]);
            float2 f0 = __half22float2(*reinterpret_cast<__half2*>(&v.x));
            float2 f1 = __half22float2(*reinterpret_cast<__half2*>(&v.y));
            acc.x = fmaf(c, f0.x, acc.x);
            acc.y = fmaf(c, f0.y, acc.y);
            acc.z = fmaf(c, f1.x, acc.z);
            acc.w = fmaf(c, f1.y, acc.w);
        }
    }

    int n = end - base;
    if (n > 0) {
        int4 rec = make_int4(0, 0, 0, 0);
        if (lane < n) rec = __ldg(&g_erec[base + lane]);
        int cb = SECOND ? rec.z : rec.y;
        for (int i = 0; i < n; i++) {
            int   s = __shfl_sync(0xffffffffu, rec.x, i);
            float c = __int_as_float(__shfl_sync(0xffffffffu, cb, i));
            uint2 v = __ldg(&feat16[s * 32 + lane]);
            float2 f0 = __half22float2(*reinterpret_cast<__half2*>(&v.x));
            float2 f1 = __half22float2(*reinterpret_cast<__half2*>(&v.y));
            acc.x = fmaf(c, f0.x, acc.x);
            acc.y = fmaf(c, f0.y, acc.y);
            acc.z = fmaf(c, f1.x, acc.z);
            acc.w = fmaf(c, f1.y, acc.w);
        }
    }

    outf[node * 32 + lane] = acc;
    if (!SECOND) {
        __half2 a = __floats2half2_rn(acc.x, acc.y);
        __half2 b = __floats2half2_rn(acc.z, acc.w);
        uint2 o;
        o.x = *reinterpret_cast<unsigned*>(&a);
        o.y = *reinterpret_cast<unsigned*>(&b);
        g_f1h[node * 32 + lane] = o;
    }
}

// ---------------- 3xTF32 helpers ---------------------------------------------
__device__ __forceinline__ unsigned f2tf(float x) {
    unsigned r;
    asm("cvt.rna.tf32.f32 %0, %1;" : "=r"(r) : "f"(x));
    return r;
}

__device__ __forceinline__ void mma8(float* d, const unsigned* a, const unsigned* b) {
    asm volatile("mma.sync.aligned.m16n8k8.row.col.f32.tf32.tf32.f32 "
                 "{%0,%1,%2,%3},{%4,%5,%6,%7},{%8,%9},{%0,%1,%2,%3};"
                 : "+f"(d[0]), "+f"(d[1]), "+f"(d[2]), "+f"(d[3])
                 : "r"(a[0]), "r"(a[1]), "r"(a[2]), "r"(a[3]),
                   "r"(b[0]), "r"(b[1]));
}

// ---------------- fused GEMM (3xTF32 mma) + bias + LayerNorm + ReLU ----------
// 256 threads (8 warps), TM=32 nodes/block. Warp w: rows [16*(w>>2), +16),
// cols [32*(w&3), +32) as 4 n-tiles of 8. K=384 = 48 k-steps of 8.
// Dynamic smem: sA[32][388] fp32 | sx[32][132] | smu[32] | srs[32]
#define SAPAD 388
#define SXPAD 132
#define OUT_SMEM ((32 * SAPAD + 32 * SXPAD + 64) * 4)

__global__ void __launch_bounds__(256) out_kernel(
    const float* __restrict__ h,
    const float* __restrict__ W,      // [128, 384] row-major
    const float* __restrict__ bias,
    const float* __restrict__ gamma,
    const float* __restrict__ beta,
    float* __restrict__ out)
{
    constexpr int TM = 32;
    extern __shared__ float dyn[];
    float* sA  = dyn;                       // [TM][SAPAD]
    float* sx  = dyn + TM * SAPAD;          // [TM][SXPAD]
    float* smu = sx + TM * SXPAD;           // [TM]
    float* srs = smu + TM;                  // [TM]

    int tid   = threadIdx.x;
    int warp  = tid >> 5;
    int lane  = tid & 31;
    int node0 = blockIdx.x * TM;

    // ---- load feature tile: feats = [h, f1*norm, f2*norm], 96 float4/node ----
    for (int idx = tid; idx < TM * 96; idx += 256) {
        int m = idx / 96, c = idx % 96;
        int node = min(node0 + m, N_NODES - 1);
        float4 v;
        if (c < 32) {
            v = __ldg(&((const float4*)h)[node * 32 + c]);
        } else {
            float nn = g_norm[node];
            const float4* ptr = (c < 64) ? (const float4*)g_f1 : (const float4*)g_f2;
            int cc = (c < 64) ? (c - 32) : (c - 64);
            v = ptr[node * 32 + cc];
            v.x *= nn; v.y *= nn; v.z *= nn; v.w *= nn;
        }
        *(float4*)&sA[m * SAPAD + c * 4] = v;
    }
    __syncthreads();

    // ---- 3xTF32 mma: D[16 x 32] per warp ----
    int g  = lane >> 2;     // group 0..7
    int tg = lane & 3;      // thread-in-group 0..3
    int mrow = (warp >> 2) * 16;
    int wcol = (warp & 3) * 32;

    float acc[4][4];
#pragma unroll
    for (int nt = 0; nt < 4; nt++)
#pragma unroll
        for (int i = 0; i < 4; i++) acc[nt][i] = 0.0f;

#pragma unroll 4
    for (int k0 = 0; k0 < 48; k0++) {
        int kk = k0 * 8;
        float a0 = sA[(mrow + g    ) * SAPAD + kk + tg];
        float a1 = sA[(mrow + g + 8) * SAPAD + kk + tg];
        float a2 = sA[(mrow + g    ) * SAPAD + kk + tg + 4];
        float a3 = sA[(mrow + g + 8) * SAPAD + kk + tg + 4];

        unsigned ah[4] = { f2tf(a0), f2tf(a1), f2tf(a2), f2tf(a3) };
        unsigned al[4] = {
            f2tf(a0 - __uint_as_float(ah[0])),
            f2tf(a1 - __uint_as_float(ah[1])),
            f2tf(a2 - __uint_as_float(ah[2])),
            f2tf(a3 - __uint_as_float(ah[3]))
        };

#pragma unroll
        for (int nt = 0; nt < 4; nt++) {
            int n = wcol + nt * 8 + g;
            float b0f = __ldg(&W[n * D_IN3 + kk + tg]);
            float b1f = __ldg(&W[n * D_IN3 + kk + tg + 4]);
            unsigned bh[2] = { f2tf(b0f), f2tf(b1f) };
            unsigned bl[2] = {
                f2tf(b0f - __uint_as_float(bh[0])),
                f2tf(b1f - __uint_as_float(bh[1]))
            };
            mma8(acc[nt], ah, bh);
            mma8(acc[nt], al, bh);
            mma8(acc[nt], ah, bl);
        }
    }

    // ---- write acc (+bias) into sx ----
#pragma unroll
    for (int nt = 0; nt < 4; nt++) {
        int col = wcol + nt * 8 + 2 * tg;
        float b0 = __ldg(&bias[col]);
        float b1 = __ldg(&bias[col + 1]);
        sx[(mrow + g    ) * SXPAD + col    ] = acc[nt][0] + b0;
        sx[(mrow + g    ) * SXPAD + col + 1] = acc[nt][1] + b1;
        sx[(mrow + g + 8) * SXPAD + col    ] = acc[nt][2] + b0;
        sx[(mrow + g + 8) * SXPAD + col + 1] = acc[nt][3] + b1;
    }
    __syncthreads();

    // ---- LayerNorm stats: each warp reduces 4 rows ----
    for (int m = warp; m < TM; m += 8) {
        float s = 0.0f, ss = 0.0f;
#pragma unroll
        for (int c = lane; c < D; c += 32) {
            float v = sx[m * SXPAD + c];
            s += v; ss += v * v;
        }
#pragma unroll
        for (int o = 16; o; o >>= 1) {
            s  += __shfl_xor_sync(0xffffffffu, s,  o);
            ss += __shfl_xor_sync(0xffffffffu, ss, o);
        }
        if (lane == 0) {
            float mu  = s * (1.0f / D);
            float var = ss * (1.0f / D) - mu * mu;
            smu[m] = mu;
            srs[m] = rsqrtf(var + LN_EPS);
        }
    }
    __syncthreads();

    // ---- normalize + relu + store ----
    int j     = tid & 127;
    int mbase = (tid >> 7) * 16;
    float gm = __ldg(&gamma[j]);
    float be = __ldg(&beta[j]);
#pragma unroll
    for (int mm = 0; mm < 16; mm++) {
        int m = mbase + mm;
        int node = node0 + m;
        if (node < N_NODES) {
            float v = (sx[m * SXPAD + j] - smu[m]) * srs[m] * gm + be;
            out[node * D + j] = fmaxf(v, 0.0f);
        }
    }
}

// ---------------- launch -----------------------------------------------------
extern "C" void kernel_launch(void* const* d_in, const int* in_sizes, int n_in,
                              void* d_out, int out_size)
{
    const float* h     = (const float*)d_in[0];
    const float* ew    = (const float*)d_in[1];
    const float* W     = (const float*)d_in[2];
    const float* bias  = (const float*)d_in[3];
    const float* gamma = (const float*)d_in[4];
    const float* beta  = (const float*)d_in[5];
    const int*   src   = (const int*)d_in[6];
    const int*   dst   = (const int*)d_in[7];
    float*       out   = (float*)d_out;

    void* cntPtr; cudaGetSymbolAddress(&cntPtr, g_cnt);
    void* f1Ptr;  cudaGetSymbolAddress(&f1Ptr,  g_f1);
    void* f2Ptr;  cudaGetSymbolAddress(&f2Ptr,  g_f2);
    void* h16Ptr; cudaGetSymbolAddress(&h16Ptr, g_h16);
    void* f1hPtr; cudaGetSymbolAddress(&f1hPtr, g_f1h);

    static bool attr_set = false;
    if (!attr_set) {
        cudaFuncSetAttribute(out_kernel,
                             cudaFuncAttributeMaxDynamicSharedMemorySize, OUT_SMEM);
        attr_set = true;
    }

    cudaMemsetAsync(cntPtr, 0, N_NODES * sizeof(int));
    conv_kernel<<<(N_NODES * 32 + 255) / 256, 256>>>((const float4*)h);
    hist_kernel<<<(N_EDGES + 255) / 256, 256>>>(dst);
    scan_kernel<<<1, 1024>>>();
    scatter_kernel<<<(N_EDGES / 2 + 255) / 256, 256>>>(ew, src, dst);

    const int hopBlocks = (N_NODES * 32 + 255) / 256;   // warp per node
    hop_csr<0><<<hopBlocks, 256>>>((const uint2*)h16Ptr, (float4*)f1Ptr);
    hop_csr<1><<<hopBlocks, 256>>>((const uint2*)f1hPtr, (float4*)f2Ptr);

    out_kernel<<<(N_NODES + 31) / 32, 256, OUT_SMEM>>>(h, W, bias, gamma, beta, out);
}

// round 6
// speedup vs baseline: 1.7902x; 1.1150x over previous
#include <cuda_runtime.h>
#include <cuda_fp16.h>

#define N_NODES 10000
#define N_EDGES 640000
#define D       128
#define D_IN3   384   // (K_HOPS+1)*D
#define LN_EPS  1e-5f

// ---------------- scratch (device globals; no allocation allowed) -----------
__device__ int    g_cnt [N_NODES];        // in-degree histogram
__device__ int    g_row [N_NODES + 1];    // CSR row offsets (by dst)
__device__ int    g_woff[N_NODES];        // scatter write cursors
__device__ float  g_norm[N_NODES];
__device__ int4   g_erec[N_EDGES];        // {src, c1 bits, c2 bits, 0} sorted by dst
__device__ float  g_f1  [N_NODES * D];    // un-normalized hop-1 aggregate (fp32)
__device__ float  g_f2  [N_NODES * D];    // un-normalized hop-2 aggregate (fp32)
__device__ uint2  g_h16 [N_NODES * 32];   // h as fp16   (gather payload, 8B/lane)
__device__ uint2  g_f1h [N_NODES * 32];   // f1 as fp16  (gather payload, 8B/lane)
__device__ float2 g_wr  [48 * 128 * 4];   // W reordered: [k0][n][tg] = {W[n][8k0+tg], W[n][8k0+tg+4]}

// ---------------- fused prep: h->fp16 conv | dst histogram | W reorder --------
// grid slices: [0,1250) conv, [1250,1875) hist (4 edges/thread), [1875,1971) W
#define PREP_CONV_BLOCKS 1250
#define PREP_HIST_BLOCKS 625
#define PREP_WR_BLOCKS   96
#define PREP_BLOCKS (PREP_CONV_BLOCKS + PREP_HIST_BLOCKS + PREP_WR_BLOCKS)

__global__ void __launch_bounds__(256) prep_kernel(
    const float4* __restrict__ h4,
    const int*    __restrict__ dst,
    const float*  __restrict__ W)
{
    int b   = blockIdx.x;
    int tid = threadIdx.x;

    if (b < PREP_CONV_BLOCKS) {
        int i = b * 256 + tid;                    // one uint2 (4 halves)
        if (i < N_NODES * 32) {
            float4 v = __ldg(&h4[i]);
            __half2 a = __floats2half2_rn(v.x, v.y);
            __half2 c = __floats2half2_rn(v.z, v.w);
            uint2 o;
            o.x = *reinterpret_cast<unsigned*>(&a);
            o.y = *reinterpret_cast<unsigned*>(&c);
            g_h16[i] = o;
        }
    } else if (b < PREP_CONV_BLOCKS + PREP_HIST_BLOCKS) {
        int t  = (b - PREP_CONV_BLOCKS) * 256 + tid;   // 4 edges per thread
        int4 d4 = __ldg(&((const int4*)dst)[t]);
        asm volatile("red.global.add.u32 [%0], %1;" :: "l"(&g_cnt[d4.x]), "r"(1) : "memory");
        asm volatile("red.global.add.u32 [%0], %1;" :: "l"(&g_cnt[d4.y]), "r"(1) : "memory");
        asm volatile("red.global.add.u32 [%0], %1;" :: "l"(&g_cnt[d4.z]), "r"(1) : "memory");
        asm volatile("red.global.add.u32 [%0], %1;" :: "l"(&g_cnt[d4.w]), "r"(1) : "memory");
    } else {
        int idx = (b - PREP_CONV_BLOCKS - PREP_HIST_BLOCKS) * 256 + tid;  // 24576 total
        int tg = idx & 3;
        int n  = (idx >> 2) & 127;
        int k0 = idx >> 9;
        g_wr[idx] = make_float2(__ldg(&W[n * D_IN3 + k0 * 8 + tg]),
                                __ldg(&W[n * D_IN3 + k0 * 8 + tg + 4]));
    }
}

// ---------------- single-block prefix scan + norm -----------------------------
__global__ void __launch_bounds__(1024) scan_kernel() {
    __shared__ int ts[1024];
    int t = threadIdx.x;
    int b = t * 10;
    int e = min(b + 10, N_NODES);

    int s = 0;
    for (int i = b; i < e; i++) s += g_cnt[i];
    ts[t] = s;
    __syncthreads();

    for (int o = 1; o < 1024; o <<= 1) {
        int v = (t >= o) ? ts[t - o] : 0;
        __syncthreads();
        ts[t] += v;
        __syncthreads();
    }
    int off = (t == 0) ? 0 : ts[t - 1];

    for (int i = b; i < e; i++) {
        int c = g_cnt[i];
        g_row[i]  = off;
        g_woff[i] = off;
        g_norm[i] = rsqrtf(fmaxf((float)c, 1.0f));
        off += c;
    }
    if (t == 1023) g_row[N_NODES] = N_EDGES;
}

// ---------------- scatter edges into CSR order (4-wide ILP) -------------------
__global__ void __launch_bounds__(256) scatter_kernel(
    const float* __restrict__ ew,
    const int*   __restrict__ src,
    const int*   __restrict__ dst)
{
    int t = blockIdx.x * blockDim.x + threadIdx.x;   // 4 edges per thread
    int4   d4 = __ldg(&((const int4*)dst)[t]);
    int4   s4 = __ldg(&((const int4*)src)[t]);
    float4 w4 = __ldg(&((const float4*)ew)[t]);

    // 4 independent atomics issue back-to-back -> overlapped 318cyc latency
    int p0 = atomicAdd(&g_woff[d4.x], 1);
    int p1 = atomicAdd(&g_woff[d4.y], 1);
    int p2 = atomicAdd(&g_woff[d4.z], 1);
    int p3 = atomicAdd(&g_woff[d4.w], 1);

    float n0 = __ldg(&g_norm[s4.x]);
    float n1 = __ldg(&g_norm[s4.y]);
    float n2 = __ldg(&g_norm[s4.z]);
    float n3 = __ldg(&g_norm[s4.w]);

    float c10 = w4.x * n0, c11 = w4.y * n1, c12 = w4.z * n2, c13 = w4.w * n3;

    g_erec[p0] = make_int4(s4.x, __float_as_int(c10), __float_as_int(c10 * n0), 0);
    g_erec[p1] = make_int4(s4.y, __float_as_int(c11), __float_as_int(c11 * n1), 0);
    g_erec[p2] = make_int4(s4.z, __float_as_int(c12), __float_as_int(c12 * n2), 0);
    g_erec[p3] = make_int4(s4.w, __float_as_int(c13), __float_as_int(c13 * n3), 0);
}

// ---------------- gather-based propagation hop (warp per node, fp16 gather) ---
template <int SECOND>
__global__ void __launch_bounds__(256, 4) hop_csr(const uint2* __restrict__ feat16,
                                                  float4* __restrict__ outf)
{
    int lane = threadIdx.x & 31;
    int node = (blockIdx.x * blockDim.x + threadIdx.x) >> 5;
    if (node >= N_NODES) return;

    int beg = g_row[node];
    int end = g_row[node + 1];

    float4 acc = make_float4(0.f, 0.f, 0.f, 0.f);
    int base = beg;

    for (; base + 32 <= end; base += 32) {
        int4 rec = __ldg(&g_erec[base + lane]);
        int cb = SECOND ? rec.z : rec.y;
#pragma unroll
        for (int i = 0; i < 32; i++) {
            int   s = __shfl_sync(0xffffffffu, rec.x, i);
            float c = __int_as_float(__shfl_sync(0xffffffffu, cb, i));
            uint2 v = __ldg(&feat16[s * 32 + lane]);
            float2 f0 = __half22float2(*reinterpret_cast<__half2*>(&v.x));
            float2 f1 = __half22float2(*reinterpret_cast<__half2*>(&v.y));
            acc.x = fmaf(c, f0.x, acc.x);
            acc.y = fmaf(c, f0.y, acc.y);
            acc.z = fmaf(c, f1.x, acc.z);
            acc.w = fmaf(c, f1.y, acc.w);
        }
    }

    int n = end - base;
    if (n > 0) {
        int4 rec = make_int4(0, 0, 0, 0);
        if (lane < n) rec = __ldg(&g_erec[base + lane]);
        int cb = SECOND ? rec.z : rec.y;
        for (int i = 0; i < n; i++) {
            int   s = __shfl_sync(0xffffffffu, rec.x, i);
            float c = __int_as_float(__shfl_sync(0xffffffffu, cb, i));
            uint2 v = __ldg(&feat16[s * 32 + lane]);
            float2 f0 = __half22float2(*reinterpret_cast<__half2*>(&v.x));
            float2 f1 = __half22float2(*reinterpret_cast<__half2*>(&v.y));
            acc.x = fmaf(c, f0.x, acc.x);
            acc.y = fmaf(c, f0.y, acc.y);
            acc.z = fmaf(c, f1.x, acc.z);
            acc.w = fmaf(c, f1.y, acc.w);
        }
    }

    outf[node * 32 + lane] = acc;
    if (!SECOND) {
        __half2 a = __floats2half2_rn(acc.x, acc.y);
        __half2 b = __floats2half2_rn(acc.z, acc.w);
        uint2 o;
        o.x = *reinterpret_cast<unsigned*>(&a);
        o.y = *reinterpret_cast<unsigned*>(&b);
        g_f1h[node * 32 + lane] = o;
    }
}

// ---------------- 3xTF32 helpers ---------------------------------------------
__device__ __forceinline__ unsigned f2tf(float x) {
    unsigned r;
    asm("cvt.rna.tf32.f32 %0, %1;" : "=r"(r) : "f"(x));
    return r;
}

__device__ __forceinline__ void mma8(float* d, const unsigned* a, const unsigned* b) {
    asm volatile("mma.sync.aligned.m16n8k8.row.col.f32.tf32.tf32.f32 "
                 "{%0,%1,%2,%3},{%4,%5,%6,%7},{%8,%9},{%0,%1,%2,%3};"
                 : "+f"(d[0]), "+f"(d[1]), "+f"(d[2]), "+f"(d[3])
                 : "r"(a[0]), "r"(a[1]), "r"(a[2]), "r"(a[3]),
                   "r"(b[0]), "r"(b[1]));
}

// ---------------- fused GEMM (3xTF32 mma) + bias + LayerNorm + ReLU ----------
// 256 threads (8 warps), TM=32. B loads via reordered g_wr -> 1 coalesced
// LDG.64 per (k0, n-tile): address = k0*512 + ncol*4 + lane.
#define SAPAD 388
#define SXPAD 132
#define OUT_SMEM ((32 * SAPAD + 32 * SXPAD + 64) * 4)

__global__ void __launch_bounds__(256) out_kernel(
    const float* __restrict__ h,
    const float* __restrict__ bias,
    const float* __restrict__ gamma,
    const float* __restrict__ beta,
    float* __restrict__ out)
{
    constexpr int TM = 32;
    extern __shared__ float dyn[];
    float* sA  = dyn;                       // [TM][SAPAD]
    float* sx  = dyn + TM * SAPAD;          // [TM][SXPAD]
    float* smu = sx + TM * SXPAD;           // [TM]
    float* srs = smu + TM;                  // [TM]

    int tid   = threadIdx.x;
    int warp  = tid >> 5;
    int lane  = tid & 31;
    int node0 = blockIdx.x * TM;

    for (int idx = tid; idx < TM * 96; idx += 256) {
        int m = idx / 96, c = idx % 96;
        int node = min(node0 + m, N_NODES - 1);
        float4 v;
        if (c < 32) {
            v = __ldg(&((const float4*)h)[node * 32 + c]);
        } else {
            float nn = g_norm[node];
            const float4* ptr = (c < 64) ? (const float4*)g_f1 : (const float4*)g_f2;
            int cc = (c < 64) ? (c - 32) : (c - 64);
            v = ptr[node * 32 + cc];
            v.x *= nn; v.y *= nn; v.z *= nn; v.w *= nn;
        }
        *(float4*)&sA[m * SAPAD + c * 4] = v;
    }
    __syncthreads();

    int g  = lane >> 2;     // group 0..7
    int tg = lane & 3;      // thread-in-group 0..3
    int mrow = (warp >> 2) * 16;
    int wcol = (warp & 3) * 32;

    float acc[4][4];
#pragma unroll
    for (int nt = 0; nt < 4; nt++)
#pragma unroll
        for (int i = 0; i < 4; i++) acc[nt][i] = 0.0f;

#pragma unroll 4
    for (int k0 = 0; k0 < 48; k0++) {
        int kk = k0 * 8;
        float a0 = sA[(mrow + g    ) * SAPAD + kk + tg];
        float a1 = sA[(mrow + g + 8) * SAPAD + kk + tg];
        float a2 = sA[(mrow + g    ) * SAPAD + kk + tg + 4];
        float a3 = sA[(mrow + g + 8) * SAPAD + kk + tg + 4];

        unsigned ah[4] = { f2tf(a0), f2tf(a1), f2tf(a2), f2tf(a3) };
        unsigned al[4] = {
            f2tf(a0 - __uint_as_float(ah[0])),
            f2tf(a1 - __uint_as_float(ah[1])),
            f2tf(a2 - __uint_as_float(ah[2])),
            f2tf(a3 - __uint_as_float(ah[3]))
        };

#pragma unroll
        for (int nt = 0; nt < 4; nt++) {
            float2 wv = __ldg(&g_wr[k0 * 512 + (wcol + nt * 8) * 4 + lane]);
            unsigned bh[2] = { f2tf(wv.x), f2tf(wv.y) };
            unsigned bl[2] = {
                f2tf(wv.x - __uint_as_float(bh[0])),
                f2tf(wv.y - __uint_as_float(bh[1]))
            };
            mma8(acc[nt], ah, bh);
            mma8(acc[nt], al, bh);
            mma8(acc[nt], ah, bl);
        }
    }

#pragma unroll
    for (int nt = 0; nt < 4; nt++) {
        int col = wcol + nt * 8 + 2 * tg;
        float b0 = __ldg(&bias[col]);
        float b1 = __ldg(&bias[col + 1]);
        sx[(mrow + g    ) * SXPAD + col    ] = acc[nt][0] + b0;
        sx[(mrow + g    ) * SXPAD + col + 1] = acc[nt][1] + b1;
        sx[(mrow + g + 8) * SXPAD + col    ] = acc[nt][2] + b0;
        sx[(mrow + g + 8) * SXPAD + col + 1] = acc[nt][3] + b1;
    }
    __syncthreads();

    for (int m = warp; m < TM; m += 8) {
        float s = 0.0f, ss = 0.0f;
#pragma unroll
        for (int c = lane; c < D; c += 32) {
            float v = sx[m * SXPAD + c];
            s += v; ss += v * v;
        }
#pragma unroll
        for (int o = 16; o; o >>= 1) {
            s  += __shfl_xor_sync(0xffffffffu, s,  o);
            ss += __shfl_xor_sync(0xffffffffu, ss, o);
        }
        if (lane == 0) {
            float mu  = s * (1.0f / D);
            float var = ss * (1.0f / D) - mu * mu;
            smu[m] = mu;
            srs[m] = rsqrtf(var + LN_EPS);
        }
    }
    __syncthreads();

    int j     = tid & 127;
    int mbase = (tid >> 7) * 16;
    float gm = __ldg(&gamma[j]);
    float be = __ldg(&beta[j]);
#pragma unroll
    for (int mm = 0; mm < 16; mm++) {
        int m = mbase + mm;
        int node = node0 + m;
        if (node < N_NODES) {
            float v = (sx[m * SXPAD + j] - smu[m]) * srs[m] * gm + be;
            out[node * D + j] = fmaxf(v, 0.0f);
        }
    }
}

// ---------------- launch -----------------------------------------------------
extern "C" void kernel_launch(void* const* d_in, const int* in_sizes, int n_in,
                              void* d_out, int out_size)
{
    const float* h     = (const float*)d_in[0];
    const float* ew    = (const float*)d_in[1];
    const float* W     = (const float*)d_in[2];
    const float* bias  = (const float*)d_in[3];
    const float* gamma = (const float*)d_in[4];
    const float* beta  = (const float*)d_in[5];
    const int*   src   = (const int*)d_in[6];
    const int*   dst   = (const int*)d_in[7];
    float*       out   = (float*)d_out;

    void* cntPtr; cudaGetSymbolAddress(&cntPtr, g_cnt);
    void* f1Ptr;  cudaGetSymbolAddress(&f1Ptr,  g_f1);
    void* f2Ptr;  cudaGetSymbolAddress(&f2Ptr,  g_f2);
    void* h16Ptr; cudaGetSymbolAddress(&h16Ptr, g_h16);
    void* f1hPtr; cudaGetSymbolAddress(&f1hPtr, g_f1h);

    static bool attr_set = false;
    if (!attr_set) {
        cudaFuncSetAttribute(out_kernel,
                             cudaFuncAttributeMaxDynamicSharedMemorySize, OUT_SMEM);
        attr_set = true;
    }

    cudaMemsetAsync(cntPtr, 0, N_NODES * sizeof(int));
    prep_kernel<<<PREP_BLOCKS, 256>>>((const float4*)h, dst, W);
    scan_kernel<<<1, 1024>>>();
    scatter_kernel<<<N_EDGES / 4 / 256, 256>>>(ew, src, dst);

    const int hopBlocks = (N_NODES * 32 + 255) / 256;   // warp per node
    hop_csr<0><<<hopBlocks, 256>>>((const uint2*)h16Ptr, (float4*)f1Ptr);
    hop_csr<1><<<hopBlocks, 256>>>((const uint2*)f1hPtr, (float4*)f2Ptr);

    out_kernel<<<(N_NODES + 31) / 32, 256, OUT_SMEM>>>(h, bias, gamma, beta, out);
}